// round 7
// baseline (speedup 1.0000x reference)
#include <cuda_runtime.h>
#include <math.h>

// Fixed problem shapes
#define TT 32      // T
#define NN 8       // neighbors
#define DD 64      // embedding dim
#define NRR 32     // num relations
#define BMAX 512

// Partial sums: [side][b][half][dim]  (always fully written per call)
__device__ __align__(16) float g_part[2 * BMAX * 2 * DD];

// ---------------------------------------------------------------------------
// Kernel A: block = (side, b, half). 128 threads (4 warps); each warp owns
// 8 units (L*T/2 per block / 4 warps), processed in batches of 4:
//   Phase A: gather + folded attention -> x into sX
//   Phase B: batched matvec vs sW (float4 x broadcasts), ELU, accumulate
// Folded logit: pi = e_h.w1 + rdot[r] + e_t.w3,
//   w_k = W @ a_k,  rdot[r] = dot(R[r], w2) precomputed per block.
// Base terms (mean of E[h0]) distributed across halves; item extra in
// (side=1, q=0). Block-reduced partial -> g_part.
// ---------------------------------------------------------------------------
__global__ __launch_bounds__(128, 10) void ckgat_part(
    const int* __restrict__ items,
    const int* __restrict__ user_h,  const int* __restrict__ user_t,
    const int* __restrict__ user_nh, const int* __restrict__ user_nr, const int* __restrict__ user_nt,
    const int* __restrict__ item_h,  const int* __restrict__ item_t,
    const int* __restrict__ item_nh, const int* __restrict__ item_nr, const int* __restrict__ item_nt,
    const float* __restrict__ E,     // entity_emb [NE,64]
    const float* __restrict__ R,     // relation_emb [32,64]
    const float* __restrict__ W,     // W_GAT [64,64]
    const float* __restrict__ aG,    // a_GAT [3*64]
    int B, int L)
{
    __shared__ float  sW[DD * DD];       // 16 KB
    __shared__ float  sw[3 * DD];        // folded W@a slices
    __shared__ float  srd[NRR];          // rdot per relation
    __shared__ float4 sX[4][4][DD / 4];  // warp, slot, dim/4: 4 KB
    __shared__ float2 sAcc[4][32];       // 1 KB

    const int tid  = threadIdx.x;
    const int lane = tid & 31;
    const int warp = tid >> 5;           // 0..3
    const int b    = blockIdx.x % B;
    const int sq   = blockIdx.x / B;
    const int side = sq & 1;             // 0 = user, 1 = item
    const int q    = sq >> 1;            // half index 0/1

    // Stage W; fold w_k[d] = sum_j W[d][j]*a[k*64+j]; rdot
    for (int i = tid; i < DD * DD; i += 128) sW[i] = W[i];
    if (tid < DD) {
        float s0 = 0.f, s1 = 0.f, s2 = 0.f;
        #pragma unroll 8
        for (int j = 0; j < DD; j++) {
            float w = W[tid * DD + j];
            s0 += w * aG[j];
            s1 += w * aG[DD + j];
            s2 += w * aG[2 * DD + j];
        }
        sw[tid] = s0; sw[DD + tid] = s1; sw[2 * DD + tid] = s2;
    }
    __syncthreads();
    if (tid < NRR) {
        float s = 0.f;
        #pragma unroll 8
        for (int d = 0; d < DD; d++) s += R[tid * DD + d] * sw[DD + d];
        srd[tid] = s;
    }
    __syncthreads();

    // Per-lane slices of folded vectors: dims {2*lane, 2*lane+1}
    const float2 w1 = *(const float2*)&sw[2 * lane];
    const float2 w3 = *(const float2*)&sw[2 * DD + 2 * lane];

    const int* nhp = side ? item_nh : user_nh;
    const int* nrp = side ? item_nr : user_nr;
    const int* ntp = side ? item_nt : user_nt;
    const int* tp  = side ? item_t  : user_t;

    float2 acc = make_float2(0.f, 0.f);

    const int half    = (L * TT) / 2;        // 32 for L=2
    const int u0      = q * half;
    const int perWarp = half / 4;            // 8
    const int nBatch  = (perWarp + 3) / 4;   // 2

    for (int jb = 0; jb < nBatch; jb++) {
        const int nIn = (perWarp - jb * 4) < 4 ? (perWarp - jb * 4) : 4;

        // -------- Phase A: attention for nIn units; x -> sX --------
        for (int i = 0; i < nIn; i++) {
            const int u = u0 + warp + 4 * (jb * 4 + i);
            const int l = u >> 5;                  // layer (T=32)
            const int t = u & 31;
            const long b3 = ((long)l * B + b) * TT + t;
            const long b4 = b3 * NN;

            // Front-batch neighbor indices (contiguous, N=8 innermost)
            const int4 nh0 = *(const int4*)&nhp[b4];
            const int4 nh1 = *(const int4*)&nhp[b4 + 4];
            const int4 nt0 = *(const int4*)&ntp[b4];
            const int4 nt1 = *(const int4*)&ntp[b4 + 4];
            const int4 nr0 = *(const int4*)&nrp[b4];
            const int4 nr1 = *(const int4*)&nrp[b4 + 4];
            const int hidx[NN] = {nh0.x, nh0.y, nh0.z, nh0.w, nh1.x, nh1.y, nh1.z, nh1.w};
            const int tidx[NN] = {nt0.x, nt0.y, nt0.z, nt0.w, nt1.x, nt1.y, nt1.z, nt1.w};
            const int ridx[NN] = {nr0.x, nr0.y, nr0.z, nr0.w, nr1.x, nr1.y, nr1.z, nr1.w};

            float2 eh[NN];
            float  pp[NN];
            #pragma unroll
            for (int n = 0; n < NN; n++) {
                float2 e  = *(const float2*)&E[(long)hidx[n] * DD + 2 * lane];
                float2 et = *(const float2*)&E[(long)tidx[n] * DD + 2 * lane];
                eh[n] = e;
                pp[n] = e.x * w1.x + e.y * w1.y
                      + et.x * w3.x + et.y * w3.y;
            }
            #pragma unroll
            for (int n = 0; n < NN; n++) {
                #pragma unroll
                for (int off = 16; off; off >>= 1)
                    pp[n] += __shfl_xor_sync(0xffffffffu, pp[n], off);
            }
            // add relation term, leaky relu, softmax over 8 (redundant per lane)
            float m = -1e30f;
            #pragma unroll
            for (int n = 0; n < NN; n++) {
                float p = pp[n] + srd[ridx[n]];
                p = p > 0.f ? p : 0.2f * p;
                pp[n] = p;
                m = fmaxf(m, p);
            }
            float s = 0.f;
            #pragma unroll
            for (int n = 0; n < NN; n++) { pp[n] = __expf(pp[n] - m); s += pp[n]; }
            const float inv = 1.f / s;

            const int tix = tp[b3];
            float2 x = *(const float2*)&E[(long)tix * DD + 2 * lane];
            #pragma unroll
            for (int n = 0; n < NN; n++) {
                const float a_ = pp[n] * inv;
                x.x += a_ * eh[n].x;
                x.y += a_ * eh[n].y;
            }
            ((float2*)&sX[warp][i][0])[lane] = x;
        }
        __syncwarp();

        // -------- Phase B: batched matvec y_i = elu(x_i @ W) --------
        const float2* sW2 = (const float2*)sW;   // sW2[d*32 + lane]
        float2 y[4];
        #pragma unroll
        for (int i = 0; i < 4; i++) y[i] = make_float2(0.f, 0.f);
        #pragma unroll 4
        for (int d4 = 0; d4 < DD / 4; d4++) {
            const float2 wr0 = sW2[(d4 * 4 + 0) * 32 + lane];
            const float2 wr1 = sW2[(d4 * 4 + 1) * 32 + lane];
            const float2 wr2 = sW2[(d4 * 4 + 2) * 32 + lane];
            const float2 wr3 = sW2[(d4 * 4 + 3) * 32 + lane];
            #pragma unroll
            for (int i = 0; i < 4; i++) {
                const float4 xv = sX[warp][i][d4];   // broadcast
                y[i].x += xv.x * wr0.x + xv.y * wr1.x + xv.z * wr2.x + xv.w * wr3.x;
                y[i].y += xv.x * wr0.y + xv.y * wr1.y + xv.z * wr2.y + xv.w * wr3.y;
            }
        }
        for (int i = 0; i < nIn; i++) {
            float y0 = y[i].x, y1 = y[i].y;
            y0 = y0 > 0.f ? y0 : (__expf(y0) - 1.f);
            y1 = y1 > 0.f ? y1 : (__expf(y1) - 1.f);
            acc.x += y0;
            acc.y += y1;
        }
        __syncwarp();
    }

    // Base term: this half covers t in [q*16, q*16+16); warp takes 4 t's
    {
        const int* hp = side ? item_h : user_h;
        const float sc = 1.f / (float)TT;
        const int tb = q * (TT / 2) + warp * 4;
        for (int t = tb; t < tb + 4; t++) {
            int hi = hp[(long)b * TT + t];
            float2 e = *(const float2*)&E[(long)hi * DD + 2 * lane];
            acc.x += e.x * sc;
            acc.y += e.y * sc;
        }
    }
    // Item-side extra: E[items[b]] (once, in half 0)
    if (side == 1 && q == 0 && warp == 0) {
        int ii = items[b];
        float2 e = *(const float2*)&E[(long)ii * DD + 2 * lane];
        acc.x += e.x;
        acc.y += e.y;
    }

    sAcc[warp][lane] = acc;
    __syncthreads();
    if (warp == 0) {
        float2 r = sAcc[0][lane];
        #pragma unroll
        for (int w = 1; w < 4; w++) {
            r.x += sAcc[w][lane].x;
            r.y += sAcc[w][lane].y;
        }
        *(float2*)&g_part[(((long)side * B + b) * 2 + q) * DD + 2 * lane] = r;
    }
}

// ---------------------------------------------------------------------------
// Kernel B: per b, sum halves, dot(e_u, e_v), sigmoid -> out[b]
// ---------------------------------------------------------------------------
__global__ void ckgat_dot(float* __restrict__ out, int B) {
    const int lane = threadIdx.x & 31;
    const int b = blockIdx.x * 8 + (threadIdx.x >> 5);
    if (b >= B) return;
    const float2* pu0 = (const float2*)&g_part[(((long)0 * B + b) * 2 + 0) * DD];
    const float2* pu1 = (const float2*)&g_part[(((long)0 * B + b) * 2 + 1) * DD];
    const float2* pv0 = (const float2*)&g_part[(((long)1 * B + b) * 2 + 0) * DD];
    const float2* pv1 = (const float2*)&g_part[(((long)1 * B + b) * 2 + 1) * DD];
    float2 u0 = pu0[lane], u1 = pu1[lane];
    float2 v0 = pv0[lane], v1 = pv1[lane];
    float ux = u0.x + u1.x, uy = u0.y + u1.y;
    float vx = v0.x + v1.x, vy = v0.y + v1.y;
    float d = ux * vx + uy * vy;
    #pragma unroll
    for (int off = 16; off; off >>= 1)
        d += __shfl_xor_sync(0xffffffffu, d, off);
    if (lane == 0) out[b] = 1.f / (1.f + __expf(-d));
}

// ---------------------------------------------------------------------------
// launch. Inputs (metadata order):
//  0 items, 1 user_h, 2 user_r, 3 user_t, 4 user_nh, 5 user_nr, 6 user_nt,
//  7 item_h, 8 item_r, 9 item_t, 10 item_nh, 11 item_nr, 12 item_nt,
//  13 entity_emb, 14 relation_emb, 15 W_GAT, 16 a_GAT
// ---------------------------------------------------------------------------
extern "C" void kernel_launch(void* const* d_in, const int* in_sizes, int n_in,
                              void* d_out, int out_size) {
    const int*   items   = (const int*)d_in[0];
    const int*   user_h  = (const int*)d_in[1];
    const int*   user_t  = (const int*)d_in[3];
    const int*   user_nh = (const int*)d_in[4];
    const int*   user_nr = (const int*)d_in[5];
    const int*   user_nt = (const int*)d_in[6];
    const int*   item_h  = (const int*)d_in[7];
    const int*   item_t  = (const int*)d_in[9];
    const int*   item_nh = (const int*)d_in[10];
    const int*   item_nr = (const int*)d_in[11];
    const int*   item_nt = (const int*)d_in[12];
    const float* E       = (const float*)d_in[13];
    const float* R       = (const float*)d_in[14];
    const float* W       = (const float*)d_in[15];
    const float* a       = (const float*)d_in[16];
    float* out = (float*)d_out;

    const int B = in_sizes[0];
    int L = in_sizes[1] / (B * TT);
    if (L < 1) L = 1;

    ckgat_part<<<4 * B, 128>>>(items, user_h, user_t, user_nh, user_nr, user_nt,
                               item_h, item_t, item_nh, item_nr, item_nt,
                               E, R, W, a, B, L);
    ckgat_dot<<<(B + 7) / 8, 256>>>(out, B);
}

// round 9
// speedup vs baseline: 1.0038x; 1.0038x over previous
#include <cuda_runtime.h>
#include <math.h>

// Fixed problem shapes
#define TT 32      // T
#define NN 8       // neighbors
#define DD 64      // embedding dim
#define NRR 32     // num relations
#define BMAX 512

// Partial sums: [side][b][half][dim]  (always fully written per call)
__device__ __align__(16) float g_part[2 * BMAX * 2 * DD];

// ---------------------------------------------------------------------------
// Kernel A: block = (side, b, half). 128 threads (4 warps); each warp owns
// 8 units (L*T/2 per block / 4 warps), processed in batches of 4:
//   Phase A: gather + folded attention -> x into sX
//   Phase B: batched matvec vs sW (float4 x broadcasts), ELU, accumulate
// Folded logit: pi = e_h.w1 + rdot[r] + e_t.w3,
//   w_k = W @ a_k,  rdot[r] = dot(R[r], w2) precomputed per block.
// Base terms (mean of E[h0]) distributed across halves; item extra in
// (side=1, q=0). Block-reduced partial -> g_part.
// ---------------------------------------------------------------------------
__global__ __launch_bounds__(128, 10) void ckgat_part(
    const int* __restrict__ items,
    const int* __restrict__ user_h,  const int* __restrict__ user_t,
    const int* __restrict__ user_nh, const int* __restrict__ user_nr, const int* __restrict__ user_nt,
    const int* __restrict__ item_h,  const int* __restrict__ item_t,
    const int* __restrict__ item_nh, const int* __restrict__ item_nr, const int* __restrict__ item_nt,
    const float* __restrict__ E,     // entity_emb [NE,64]
    const float* __restrict__ R,     // relation_emb [32,64]
    const float* __restrict__ W,     // W_GAT [64,64]
    const float* __restrict__ aG,    // a_GAT [3*64]
    int B, int L)
{
    __shared__ float  sW[DD * DD];       // 16 KB
    __shared__ float  sw[3 * DD];        // folded W@a slices
    __shared__ float  srd[NRR];          // rdot per relation
    __shared__ float4 sX[4][4][DD / 4];  // warp, slot, dim/4: 4 KB
    __shared__ float2 sAcc[4][32];       // 1 KB

    const int tid  = threadIdx.x;
    const int lane = tid & 31;
    const int warp = tid >> 5;           // 0..3
    const int b    = blockIdx.x % B;
    const int sq   = blockIdx.x / B;
    const int side = sq & 1;             // 0 = user, 1 = item
    const int q    = sq >> 1;            // half index 0/1

    // Stage W; fold w_k[d] = sum_j W[d][j]*a[k*64+j]; rdot
    for (int i = tid; i < DD * DD; i += 128) sW[i] = W[i];
    if (tid < DD) {
        float s0 = 0.f, s1 = 0.f, s2 = 0.f;
        #pragma unroll 8
        for (int j = 0; j < DD; j++) {
            float w = W[tid * DD + j];
            s0 += w * aG[j];
            s1 += w * aG[DD + j];
            s2 += w * aG[2 * DD + j];
        }
        sw[tid] = s0; sw[DD + tid] = s1; sw[2 * DD + tid] = s2;
    }
    __syncthreads();
    if (tid < NRR) {
        float s = 0.f;
        #pragma unroll 8
        for (int d = 0; d < DD; d++) s += R[tid * DD + d] * sw[DD + d];
        srd[tid] = s;
    }
    __syncthreads();

    // Per-lane slices of folded vectors: dims {2*lane, 2*lane+1}
    const float2 w1 = *(const float2*)&sw[2 * lane];
    const float2 w3 = *(const float2*)&sw[2 * DD + 2 * lane];

    const int* nhp = side ? item_nh : user_nh;
    const int* nrp = side ? item_nr : user_nr;
    const int* ntp = side ? item_nt : user_nt;
    const int* tp  = side ? item_t  : user_t;

    float2 acc = make_float2(0.f, 0.f);

    const int half    = (L * TT) / 2;        // 32 for L=2
    const int u0      = q * half;
    const int perWarp = half / 4;            // 8
    const int nBatch  = (perWarp + 3) / 4;   // 2

    for (int jb = 0; jb < nBatch; jb++) {
        const int nIn = (perWarp - jb * 4) < 4 ? (perWarp - jb * 4) : 4;

        // -------- Phase A: attention for nIn units; x -> sX --------
        for (int i = 0; i < nIn; i++) {
            const int u = u0 + warp + 4 * (jb * 4 + i);
            const int l = u >> 5;                  // layer (T=32)
            const int t = u & 31;
            const long b3 = ((long)l * B + b) * TT + t;
            const long b4 = b3 * NN;

            // Front-batch neighbor indices (contiguous, N=8 innermost)
            const int4 nh0 = *(const int4*)&nhp[b4];
            const int4 nh1 = *(const int4*)&nhp[b4 + 4];
            const int4 nt0 = *(const int4*)&ntp[b4];
            const int4 nt1 = *(const int4*)&ntp[b4 + 4];
            const int4 nr0 = *(const int4*)&nrp[b4];
            const int4 nr1 = *(const int4*)&nrp[b4 + 4];
            const int hidx[NN] = {nh0.x, nh0.y, nh0.z, nh0.w, nh1.x, nh1.y, nh1.z, nh1.w};
            const int tidx[NN] = {nt0.x, nt0.y, nt0.z, nt0.w, nt1.x, nt1.y, nt1.z, nt1.w};
            const int ridx[NN] = {nr0.x, nr0.y, nr0.z, nr0.w, nr1.x, nr1.y, nr1.z, nr1.w};

            float2 eh[NN];
            float  pp[NN];
            #pragma unroll
            for (int n = 0; n < NN; n++) {
                float2 e  = *(const float2*)&E[(long)hidx[n] * DD + 2 * lane];
                float2 et = *(const float2*)&E[(long)tidx[n] * DD + 2 * lane];
                eh[n] = e;
                pp[n] = e.x * w1.x + e.y * w1.y
                      + et.x * w3.x + et.y * w3.y;
            }
            #pragma unroll
            for (int n = 0; n < NN; n++) {
                #pragma unroll
                for (int off = 16; off; off >>= 1)
                    pp[n] += __shfl_xor_sync(0xffffffffu, pp[n], off);
            }
            // add relation term, leaky relu, softmax over 8 (redundant per lane)
            float m = -1e30f;
            #pragma unroll
            for (int n = 0; n < NN; n++) {
                float p = pp[n] + srd[ridx[n]];
                p = p > 0.f ? p : 0.2f * p;
                pp[n] = p;
                m = fmaxf(m, p);
            }
            float s = 0.f;
            #pragma unroll
            for (int n = 0; n < NN; n++) { pp[n] = __expf(pp[n] - m); s += pp[n]; }
            const float inv = 1.f / s;

            const int tix = tp[b3];
            float2 x = *(const float2*)&E[(long)tix * DD + 2 * lane];
            #pragma unroll
            for (int n = 0; n < NN; n++) {
                const float a_ = pp[n] * inv;
                x.x += a_ * eh[n].x;
                x.y += a_ * eh[n].y;
            }
            ((float2*)&sX[warp][i][0])[lane] = x;
        }
        __syncwarp();

        // -------- Phase B: batched matvec y_i = elu(x_i @ W) --------
        const float2* sW2 = (const float2*)sW;   // sW2[d*32 + lane]
        float2 y[4];
        #pragma unroll
        for (int i = 0; i < 4; i++) y[i] = make_float2(0.f, 0.f);
        #pragma unroll 4
        for (int d4 = 0; d4 < DD / 4; d4++) {
            const float2 wr0 = sW2[(d4 * 4 + 0) * 32 + lane];
            const float2 wr1 = sW2[(d4 * 4 + 1) * 32 + lane];
            const float2 wr2 = sW2[(d4 * 4 + 2) * 32 + lane];
            const float2 wr3 = sW2[(d4 * 4 + 3) * 32 + lane];
            #pragma unroll
            for (int i = 0; i < 4; i++) {
                const float4 xv = sX[warp][i][d4];   // broadcast
                y[i].x += xv.x * wr0.x + xv.y * wr1.x + xv.z * wr2.x + xv.w * wr3.x;
                y[i].y += xv.x * wr0.y + xv.y * wr1.y + xv.z * wr2.y + xv.w * wr3.y;
            }
        }
        for (int i = 0; i < nIn; i++) {
            float y0 = y[i].x, y1 = y[i].y;
            y0 = y0 > 0.f ? y0 : (__expf(y0) - 1.f);
            y1 = y1 > 0.f ? y1 : (__expf(y1) - 1.f);
            acc.x += y0;
            acc.y += y1;
        }
        __syncwarp();
    }

    // Base term: this half covers t in [q*16, q*16+16); warp takes 4 t's
    {
        const int* hp = side ? item_h : user_h;
        const float sc = 1.f / (float)TT;
        const int tb = q * (TT / 2) + warp * 4;
        for (int t = tb; t < tb + 4; t++) {
            int hi = hp[(long)b * TT + t];
            float2 e = *(const float2*)&E[(long)hi * DD + 2 * lane];
            acc.x += e.x * sc;
            acc.y += e.y * sc;
        }
    }
    // Item-side extra: E[items[b]] (once, in half 0)
    if (side == 1 && q == 0 && warp == 0) {
        int ii = items[b];
        float2 e = *(const float2*)&E[(long)ii * DD + 2 * lane];
        acc.x += e.x;
        acc.y += e.y;
    }

    sAcc[warp][lane] = acc;
    __syncthreads();
    if (warp == 0) {
        float2 r = sAcc[0][lane];
        #pragma unroll
        for (int w = 1; w < 4; w++) {
            r.x += sAcc[w][lane].x;
            r.y += sAcc[w][lane].y;
        }
        *(float2*)&g_part[(((long)side * B + b) * 2 + q) * DD + 2 * lane] = r;
    }
}

// ---------------------------------------------------------------------------
// Kernel B: per b, sum halves, dot(e_u, e_v), sigmoid -> out[b]
// ---------------------------------------------------------------------------
__global__ void ckgat_dot(float* __restrict__ out, int B) {
    const int lane = threadIdx.x & 31;
    const int b = blockIdx.x * 8 + (threadIdx.x >> 5);
    if (b >= B) return;
    const float2* pu0 = (const float2*)&g_part[(((long)0 * B + b) * 2 + 0) * DD];
    const float2* pu1 = (const float2*)&g_part[(((long)0 * B + b) * 2 + 1) * DD];
    const float2* pv0 = (const float2*)&g_part[(((long)1 * B + b) * 2 + 0) * DD];
    const float2* pv1 = (const float2*)&g_part[(((long)1 * B + b) * 2 + 1) * DD];
    float2 u0 = pu0[lane], u1 = pu1[lane];
    float2 v0 = pv0[lane], v1 = pv1[lane];
    float ux = u0.x + u1.x, uy = u0.y + u1.y;
    float vx = v0.x + v1.x, vy = v0.y + v1.y;
    float d = ux * vx + uy * vy;
    #pragma unroll
    for (int off = 16; off; off >>= 1)
        d += __shfl_xor_sync(0xffffffffu, d, off);
    if (lane == 0) out[b] = 1.f / (1.f + __expf(-d));
}

// ---------------------------------------------------------------------------
// launch. Inputs (metadata order):
//  0 items, 1 user_h, 2 user_r, 3 user_t, 4 user_nh, 5 user_nr, 6 user_nt,
//  7 item_h, 8 item_r, 9 item_t, 10 item_nh, 11 item_nr, 12 item_nt,
//  13 entity_emb, 14 relation_emb, 15 W_GAT, 16 a_GAT
// ---------------------------------------------------------------------------
extern "C" void kernel_launch(void* const* d_in, const int* in_sizes, int n_in,
                              void* d_out, int out_size) {
    const int*   items   = (const int*)d_in[0];
    const int*   user_h  = (const int*)d_in[1];
    const int*   user_t  = (const int*)d_in[3];
    const int*   user_nh = (const int*)d_in[4];
    const int*   user_nr = (const int*)d_in[5];
    const int*   user_nt = (const int*)d_in[6];
    const int*   item_h  = (const int*)d_in[7];
    const int*   item_t  = (const int*)d_in[9];
    const int*   item_nh = (const int*)d_in[10];
    const int*   item_nr = (const int*)d_in[11];
    const int*   item_nt = (const int*)d_in[12];
    const float* E       = (const float*)d_in[13];
    const float* R       = (const float*)d_in[14];
    const float* W       = (const float*)d_in[15];
    const float* a       = (const float*)d_in[16];
    float* out = (float*)d_out;

    const int B = in_sizes[0];
    int L = in_sizes[1] / (B * TT);
    if (L < 1) L = 1;

    ckgat_part<<<4 * B, 128>>>(items, user_h, user_t, user_nh, user_nr, user_nt,
                               item_h, item_t, item_nh, item_nr, item_nt,
                               E, R, W, a, B, L);
    ckgat_dot<<<(B + 7) / 8, 256>>>(out, B);
}

// round 10
// speedup vs baseline: 1.5673x; 1.5613x over previous
#include <cuda_runtime.h>
#include <math.h>

// Fixed problem shapes
#define TT 32      // T
#define NN 8       // neighbors
#define DD 64      // embedding dim
#define NRR 32     // num relations

// ---------------------------------------------------------------------------
// Single fused kernel. Block = batch index b (512 blocks, 256 threads).
//   warps 0-3: user side (64 units = L*T, 16/warp), warps 4-7: item side.
// Phase A (half-warp split): lane = (half, q), q = lane&15, dims 4q..4q+3.
//   half 0 handles neighbors 0-3, half 1 neighbors 4-7. Logit:
//   pi[n] = dot(eh,w1) + rdot[r] + dot(et,w3); 4-stage butterfly within half.
// Phase B: batched matvec (8 units) vs sW, float4 x broadcasts, ELU, acc.
// ---------------------------------------------------------------------------
__global__ __launch_bounds__(256) void ckgat_fused(
    const int* __restrict__ items,
    const int* __restrict__ user_h,  const int* __restrict__ user_t,
    const int* __restrict__ user_nh, const int* __restrict__ user_nr, const int* __restrict__ user_nt,
    const int* __restrict__ item_h,  const int* __restrict__ item_t,
    const int* __restrict__ item_nh, const int* __restrict__ item_nr, const int* __restrict__ item_nt,
    const float* __restrict__ E,     // entity_emb [NE,64]
    const float* __restrict__ R,     // relation_emb [32,64]
    const float* __restrict__ W,     // W_GAT [64,64]
    const float* __restrict__ aG,    // a_GAT [3*64]
    float* __restrict__ out,
    int B, int L)
{
    __shared__ float  sW[DD * DD];       // 16 KB
    __shared__ float  sw[3 * DD];        // folded W@a slices
    __shared__ float  srd[NRR];          // rdot per relation
    __shared__ float  sX[8][8][DD];      // warp, slot, dim: 16 KB
    __shared__ float2 sAcc[8][32];       // 2 KB

    const int tid  = threadIdx.x;
    const int lane = tid & 31;
    const int warp = tid >> 5;
    const int side = warp >> 2;          // 0 = user, 1 = item
    const int wu   = warp & 3;           // warp-in-side
    const int b    = blockIdx.x;
    const int half = lane >> 4;          // 0: neighbors 0-3, 1: neighbors 4-7
    const int q    = lane & 15;          // sublane: dims 4q..4q+3

    // Stage W; fold w_k[d] = sum_j W[d][j]*a[k*64+j]
    for (int i = tid; i < DD * DD; i += 256) sW[i] = W[i];
    if (tid < DD) {
        float s0 = 0.f, s1 = 0.f, s2 = 0.f;
        #pragma unroll 8
        for (int j = 0; j < DD; j++) {
            float w = W[tid * DD + j];
            s0 += w * aG[j];
            s1 += w * aG[DD + j];
            s2 += w * aG[2 * DD + j];
        }
        sw[tid] = s0; sw[DD + tid] = s1; sw[2 * DD + tid] = s2;
    }
    __syncthreads();
    // rdot[r] = dot(R[r], w2)
    if (tid < NRR) {
        float s = 0.f;
        #pragma unroll 8
        for (int d = 0; d < DD; d++) s += R[tid * DD + d] * sw[DD + d];
        srd[tid] = s;
    }
    __syncthreads();

    // Per-lane float4 slices of folded vectors: dims 4q..4q+3
    const float4 w1q = *(const float4*)&sw[4 * q];
    const float4 w3q = *(const float4*)&sw[2 * DD + 4 * q];

    const int* nhp = side ? item_nh : user_nh;
    const int* nrp = side ? item_nr : user_nr;
    const int* ntp = side ? item_nt : user_nt;
    const int* tp  = side ? item_t  : user_t;

    float2 acc = make_float2(0.f, 0.f);

    const int nUnits  = L * TT;              // 64 for L=2
    const int perWarp = nUnits / 4;          // 16
    const int nBatch  = (perWarp + 7) / 8;   // 2

    for (int jb = 0; jb < nBatch; jb++) {
        const int nIn = (perWarp - jb * 8) < 8 ? (perWarp - jb * 8) : 8;

        // -------- Phase A: attention for nIn units; x -> sX --------
        for (int i = 0; i < nIn; i++) {
            const int u = wu + 4 * (jb * 8 + i);
            const int l = u >> 5;                  // layer (T=32)
            const int t = u & 31;
            const long b3 = ((long)l * B + b) * TT + t;
            const long b4 = b3 * NN;

            // Neighbor indices: this half's 4 neighbors
            const int4 nh4 = *(const int4*)&nhp[b4 + 4 * half];
            const int4 nt4 = *(const int4*)&ntp[b4 + 4 * half];
            const int4 nr4 = *(const int4*)&nrp[b4 + 4 * half];
            const int hj[4] = {nh4.x, nh4.y, nh4.z, nh4.w};
            const int tj[4] = {nt4.x, nt4.y, nt4.z, nt4.w};
            const int rj[4] = {nr4.x, nr4.y, nr4.z, nr4.w};

            float4 eh[4];
            float  pp[4];
            #pragma unroll
            for (int j = 0; j < 4; j++) {
                const float4 e  = *(const float4*)&E[(long)hj[j] * DD + 4 * q];
                const float4 et = *(const float4*)&E[(long)tj[j] * DD + 4 * q];
                eh[j] = e;
                pp[j] = e.x * w1q.x + e.y * w1q.y + e.z * w1q.z + e.w * w1q.w
                      + et.x * w3q.x + et.y * w3q.y + et.z * w3q.z + et.w * w3q.w;
            }
            // 4-stage butterfly within each 16-lane half (offsets 8,4,2,1)
            #pragma unroll
            for (int j = 0; j < 4; j++) {
                #pragma unroll
                for (int off = 8; off; off >>= 1)
                    pp[j] += __shfl_xor_sync(0xffffffffu, pp[j], off);
            }
            // relation term + leaky relu
            float m4 = -1e30f;
            #pragma unroll
            for (int j = 0; j < 4; j++) {
                float p = pp[j] + srd[rj[j]];
                p = p > 0.f ? p : 0.2f * p;
                pp[j] = p;
                m4 = fmaxf(m4, p);
            }
            // softmax over all 8 neighbors (cross-half max & sum)
            const float m = fmaxf(m4, __shfl_xor_sync(0xffffffffu, m4, 16));
            float s4 = 0.f;
            #pragma unroll
            for (int j = 0; j < 4; j++) { pp[j] = __expf(pp[j] - m); s4 += pp[j]; }
            const float s = s4 + __shfl_xor_sync(0xffffffffu, s4, 16);
            const float inv = 1.f / s;

            // x partial = sum of this half's 4 weighted neighbors (+ target in half 0)
            float4 x = make_float4(0.f, 0.f, 0.f, 0.f);
            #pragma unroll
            for (int j = 0; j < 4; j++) {
                const float a_ = pp[j] * inv;
                x.x += a_ * eh[j].x;
                x.y += a_ * eh[j].y;
                x.z += a_ * eh[j].z;
                x.w += a_ * eh[j].w;
            }
            if (half == 0) {
                const int tix = tp[b3];
                const float4 tg = *(const float4*)&E[(long)tix * DD + 4 * q];
                x.x += tg.x; x.y += tg.y; x.z += tg.z; x.w += tg.w;
            }
            // combine halves
            x.x += __shfl_xor_sync(0xffffffffu, x.x, 16);
            x.y += __shfl_xor_sync(0xffffffffu, x.y, 16);
            x.z += __shfl_xor_sync(0xffffffffu, x.z, 16);
            x.w += __shfl_xor_sync(0xffffffffu, x.w, 16);
            if (half == 0)
                *(float4*)&sX[warp][i][4 * q] = x;
        }
        __syncwarp();

        // -------- Phase B: batched matvec y_i = elu(x_i @ W) --------
        const float2* sW2 = (const float2*)sW;   // sW2[d*32 + lane] = W[d][2*lane..+1]
        float2 y[8];
        #pragma unroll
        for (int i = 0; i < 8; i++) y[i] = make_float2(0.f, 0.f);
        #pragma unroll 4
        for (int d4 = 0; d4 < DD / 4; d4++) {
            const float2 wr0 = sW2[(d4 * 4 + 0) * 32 + lane];
            const float2 wr1 = sW2[(d4 * 4 + 1) * 32 + lane];
            const float2 wr2 = sW2[(d4 * 4 + 2) * 32 + lane];
            const float2 wr3 = sW2[(d4 * 4 + 3) * 32 + lane];
            #pragma unroll
            for (int i = 0; i < 8; i++) {
                const float4 xv = *(const float4*)&sX[warp][i][d4 * 4];  // broadcast
                y[i].x += xv.x * wr0.x + xv.y * wr1.x + xv.z * wr2.x + xv.w * wr3.x;
                y[i].y += xv.x * wr0.y + xv.y * wr1.y + xv.z * wr2.y + xv.w * wr3.y;
            }
        }
        for (int i = 0; i < nIn; i++) {
            float y0 = y[i].x, y1 = y[i].y;
            y0 = y0 > 0.f ? y0 : (__expf(y0) - 1.f);
            y1 = y1 > 0.f ? y1 : (__expf(y1) - 1.f);
            acc.x += y0;
            acc.y += y1;
        }
        __syncwarp();
    }

    // Base term: mean over T of E[h0[b][t]]; dims {2*lane, 2*lane+1}
    {
        const int* hp = side ? item_h : user_h;
        const float sc = 1.f / (float)TT;
        for (int t = wu * 8; t < wu * 8 + 8; t++) {
            int hi = hp[(long)b * TT + t];
            float2 e = *(const float2*)&E[(long)hi * DD + 2 * lane];
            acc.x += e.x * sc;
            acc.y += e.y * sc;
        }
    }
    // Item-side extra: E[items[b]]
    if (side == 1 && wu == 0) {
        int ii = items[b];
        float2 e = *(const float2*)&E[(long)ii * DD + 2 * lane];
        acc.x += e.x;
        acc.y += e.y;
    }

    sAcc[warp][lane] = acc;
    __syncthreads();

    // Warp 0: reduce both sides, dot, sigmoid, write
    if (warp == 0) {
        float2 u = sAcc[0][lane];
        float2 v = sAcc[4][lane];
        #pragma unroll
        for (int w = 1; w < 4; w++) {
            u.x += sAcc[w][lane].x;     u.y += sAcc[w][lane].y;
            v.x += sAcc[4 + w][lane].x; v.y += sAcc[4 + w][lane].y;
        }
        float d = u.x * v.x + u.y * v.y;
        #pragma unroll
        for (int off = 16; off; off >>= 1)
            d += __shfl_xor_sync(0xffffffffu, d, off);
        if (lane == 0) out[b] = 1.f / (1.f + __expf(-d));
    }
}

// ---------------------------------------------------------------------------
// launch. Inputs (metadata order):
//  0 items, 1 user_h, 2 user_r, 3 user_t, 4 user_nh, 5 user_nr, 6 user_nt,
//  7 item_h, 8 item_r, 9 item_t, 10 item_nh, 11 item_nr, 12 item_nt,
//  13 entity_emb, 14 relation_emb, 15 W_GAT, 16 a_GAT
// ---------------------------------------------------------------------------
extern "C" void kernel_launch(void* const* d_in, const int* in_sizes, int n_in,
                              void* d_out, int out_size) {
    const int*   items   = (const int*)d_in[0];
    const int*   user_h  = (const int*)d_in[1];
    const int*   user_t  = (const int*)d_in[3];
    const int*   user_nh = (const int*)d_in[4];
    const int*   user_nr = (const int*)d_in[5];
    const int*   user_nt = (const int*)d_in[6];
    const int*   item_h  = (const int*)d_in[7];
    const int*   item_t  = (const int*)d_in[9];
    const int*   item_nh = (const int*)d_in[10];
    const int*   item_nr = (const int*)d_in[11];
    const int*   item_nt = (const int*)d_in[12];
    const float* E       = (const float*)d_in[13];
    const float* R       = (const float*)d_in[14];
    const float* W       = (const float*)d_in[15];
    const float* a       = (const float*)d_in[16];
    float* out = (float*)d_out;

    const int B = in_sizes[0];
    int L = in_sizes[1] / (B * TT);
    if (L < 1) L = 1;

    ckgat_fused<<<B, 256>>>(items, user_h, user_t, user_nh, user_nr, user_nt,
                            item_h, item_t, item_nh, item_nr, item_nt,
                            E, R, W, a, out, B, L);
}

// round 11
// speedup vs baseline: 1.6148x; 1.0303x over previous
#include <cuda_runtime.h>
#include <math.h>

// Fixed problem shapes
#define TT 32      // T
#define NN 8       // neighbors
#define DD 64      // embedding dim
#define NRR 32     // num relations
#define TDOT_MAX 100352

// Folded vectors: [0..63]=w1, [64..127]=w3
__device__ __align__(16) float g_w[2 * DD];
__device__ __align__(16) float g_rdot[NRR];
// tdot[e] = dot(E[e], w3)
__device__ __align__(16) float g_tdot[TDOT_MAX];

// ---------------------------------------------------------------------------
// Kernel 1: fold w_k = W @ a_k; rdot[r] = dot(R[r], w2). One block, 64 thr.
// ---------------------------------------------------------------------------
__global__ void ckgat_prep(const float* __restrict__ W, const float* __restrict__ aG,
                           const float* __restrict__ R) {
    __shared__ float sw2[DD];
    const int d = threadIdx.x;  // 64 threads
    float s0 = 0.f, s1 = 0.f, s2 = 0.f;
    #pragma unroll 8
    for (int j = 0; j < DD; j++) {
        float w = W[d * DD + j];
        s0 += w * aG[j];
        s1 += w * aG[DD + j];
        s2 += w * aG[2 * DD + j];
    }
    g_w[d] = s0;          // w1
    g_w[DD + d] = s2;     // w3
    sw2[d] = s1;
    __syncthreads();
    if (d < NRR) {
        float s = 0.f;
        #pragma unroll 8
        for (int k = 0; k < DD; k++) s += R[d * DD + k] * sw2[k];
        g_rdot[d] = s;
    }
}

// ---------------------------------------------------------------------------
// Kernel 2: g_tdot[e] = dot(E[e], w3). Warp per row, float2 per lane.
// Also pre-warms L2 with the whole entity table.
// ---------------------------------------------------------------------------
__global__ __launch_bounds__(256) void ckgat_tdot(const float* __restrict__ E, int NE) {
    __shared__ float sw3[DD];
    const int tid  = threadIdx.x;
    const int lane = tid & 31;
    const int warp = tid >> 5;
    if (tid < DD) sw3[tid] = g_w[DD + tid];
    __syncthreads();
    const int row = blockIdx.x * 8 + warp;
    if (row >= NE) return;
    const float2 e = *(const float2*)&E[(long)row * DD + 2 * lane];
    const float2 w = *(const float2*)&sw3[2 * lane];
    float p = e.x * w.x + e.y * w.y;
    #pragma unroll
    for (int off = 16; off; off >>= 1)
        p += __shfl_xor_sync(0xffffffffu, p, off);
    if (lane == 0) g_tdot[row] = p;
}

// ---------------------------------------------------------------------------
// Kernel 3: main fused GAT. Block = b (512 blocks, 256 threads).
//   warps 0-3: user side (16 units/warp), warps 4-7: item side.
// Phase A (half-warp split): lane = (half, q), q = lane&15, dims 4q..4q+3;
//   half 0 = neighbors 0-3, half 1 = neighbors 4-7.
//   logit = butterfly(dot64(eh, w1)) + rdot[r] + tdot[t_n]  (no et row loads!)
// Phase B: batched matvec (8 units) vs sW, float4 x broadcasts, ELU, acc.
// ---------------------------------------------------------------------------
__global__ __launch_bounds__(256) void ckgat_fused(
    const int* __restrict__ items,
    const int* __restrict__ user_h,  const int* __restrict__ user_t,
    const int* __restrict__ user_nh, const int* __restrict__ user_nr, const int* __restrict__ user_nt,
    const int* __restrict__ item_h,  const int* __restrict__ item_t,
    const int* __restrict__ item_nh, const int* __restrict__ item_nr, const int* __restrict__ item_nt,
    const float* __restrict__ E,     // entity_emb [NE,64]
    const float* __restrict__ W,     // W_GAT [64,64]
    float* __restrict__ out,
    int B, int L)
{
    __shared__ float  sW[DD * DD];       // 16 KB
    __shared__ float  sw1[DD];
    __shared__ float  srd[NRR];
    __shared__ float  sX[8][8][DD];      // warp, slot, dim: 16 KB
    __shared__ float2 sAcc[8][32];       // 2 KB

    const int tid  = threadIdx.x;
    const int lane = tid & 31;
    const int warp = tid >> 5;
    const int side = warp >> 2;          // 0 = user, 1 = item
    const int wu   = warp & 3;           // warp-in-side
    const int b    = blockIdx.x;
    const int half = lane >> 4;          // 0: neighbors 0-3, 1: neighbors 4-7
    const int q    = lane & 15;          // sublane: dims 4q..4q+3

    for (int i = tid; i < DD * DD; i += 256) sW[i] = W[i];
    if (tid < DD) sw1[tid] = g_w[tid];
    if (tid >= DD && tid < DD + NRR) srd[tid - DD] = g_rdot[tid - DD];
    __syncthreads();

    // Per-lane float4 slice of w1: dims 4q..4q+3
    const float4 w1q = *(const float4*)&sw1[4 * q];

    const int* nhp = side ? item_nh : user_nh;
    const int* nrp = side ? item_nr : user_nr;
    const int* ntp = side ? item_nt : user_nt;
    const int* tp  = side ? item_t  : user_t;

    float2 acc = make_float2(0.f, 0.f);

    const int nUnits  = L * TT;              // 64 for L=2
    const int perWarp = nUnits / 4;          // 16
    const int nBatch  = (perWarp + 7) / 8;   // 2

    for (int jb = 0; jb < nBatch; jb++) {
        const int nIn = (perWarp - jb * 8) < 8 ? (perWarp - jb * 8) : 8;

        // -------- Phase A: attention for nIn units; x -> sX --------
        for (int i = 0; i < nIn; i++) {
            const int u = wu + 4 * (jb * 8 + i);
            const int l = u >> 5;                  // layer (T=32)
            const int t = u & 31;
            const long b3 = ((long)l * B + b) * TT + t;
            const long b4 = b3 * NN;

            // This half's 4 neighbors
            const int4 nh4 = *(const int4*)&nhp[b4 + 4 * half];
            const int4 nt4 = *(const int4*)&ntp[b4 + 4 * half];
            const int4 nr4 = *(const int4*)&nrp[b4 + 4 * half];
            const int hj[4] = {nh4.x, nh4.y, nh4.z, nh4.w};
            const int tj[4] = {nt4.x, nt4.y, nt4.z, nt4.w};
            const int rj[4] = {nr4.x, nr4.y, nr4.z, nr4.w};

            float4 eh[4];
            float  pp[4];
            #pragma unroll
            for (int j = 0; j < 4; j++) {
                const float4 e = *(const float4*)&E[(long)hj[j] * DD + 4 * q];
                eh[j] = e;
                pp[j] = e.x * w1q.x + e.y * w1q.y + e.z * w1q.z + e.w * w1q.w;
            }
            // 4-stage butterfly within each 16-lane half
            #pragma unroll
            for (int j = 0; j < 4; j++) {
                #pragma unroll
                for (int off = 8; off; off >>= 1)
                    pp[j] += __shfl_xor_sync(0xffffffffu, pp[j], off);
            }
            // relation + tail-dot terms, leaky relu
            float m4 = -1e30f;
            #pragma unroll
            for (int j = 0; j < 4; j++) {
                float p = pp[j] + srd[rj[j]] + g_tdot[tj[j]];
                p = p > 0.f ? p : 0.2f * p;
                pp[j] = p;
                m4 = fmaxf(m4, p);
            }
            // softmax over all 8 neighbors (cross-half)
            const float m = fmaxf(m4, __shfl_xor_sync(0xffffffffu, m4, 16));
            float s4 = 0.f;
            #pragma unroll
            for (int j = 0; j < 4; j++) { pp[j] = __expf(pp[j] - m); s4 += pp[j]; }
            const float s = s4 + __shfl_xor_sync(0xffffffffu, s4, 16);
            const float inv = 1.f / s;

            // x partial = this half's weighted neighbors (+ target in half 0)
            float4 x = make_float4(0.f, 0.f, 0.f, 0.f);
            #pragma unroll
            for (int j = 0; j < 4; j++) {
                const float a_ = pp[j] * inv;
                x.x += a_ * eh[j].x;
                x.y += a_ * eh[j].y;
                x.z += a_ * eh[j].z;
                x.w += a_ * eh[j].w;
            }
            if (half == 0) {
                const int tix = tp[b3];
                const float4 tg = *(const float4*)&E[(long)tix * DD + 4 * q];
                x.x += tg.x; x.y += tg.y; x.z += tg.z; x.w += tg.w;
            }
            x.x += __shfl_xor_sync(0xffffffffu, x.x, 16);
            x.y += __shfl_xor_sync(0xffffffffu, x.y, 16);
            x.z += __shfl_xor_sync(0xffffffffu, x.z, 16);
            x.w += __shfl_xor_sync(0xffffffffu, x.w, 16);
            if (half == 0)
                *(float4*)&sX[warp][i][4 * q] = x;
        }
        __syncwarp();

        // -------- Phase B: batched matvec y_i = elu(x_i @ W) --------
        const float2* sW2 = (const float2*)sW;   // sW2[d*32 + lane]
        float2 y[8];
        #pragma unroll
        for (int i = 0; i < 8; i++) y[i] = make_float2(0.f, 0.f);
        #pragma unroll 4
        for (int d4 = 0; d4 < DD / 4; d4++) {
            const float2 wr0 = sW2[(d4 * 4 + 0) * 32 + lane];
            const float2 wr1 = sW2[(d4 * 4 + 1) * 32 + lane];
            const float2 wr2 = sW2[(d4 * 4 + 2) * 32 + lane];
            const float2 wr3 = sW2[(d4 * 4 + 3) * 32 + lane];
            #pragma unroll
            for (int i = 0; i < 8; i++) {
                const float4 xv = *(const float4*)&sX[warp][i][d4 * 4];  // broadcast
                y[i].x += xv.x * wr0.x + xv.y * wr1.x + xv.z * wr2.x + xv.w * wr3.x;
                y[i].y += xv.x * wr0.y + xv.y * wr1.y + xv.z * wr2.y + xv.w * wr3.y;
            }
        }
        for (int i = 0; i < nIn; i++) {
            float y0 = y[i].x, y1 = y[i].y;
            y0 = y0 > 0.f ? y0 : (__expf(y0) - 1.f);
            y1 = y1 > 0.f ? y1 : (__expf(y1) - 1.f);
            acc.x += y0;
            acc.y += y1;
        }
        __syncwarp();
    }

    // Base term: mean over T of E[h0[b][t]]; dims {2*lane, 2*lane+1}
    {
        const int* hp = side ? item_h : user_h;
        const float sc = 1.f / (float)TT;
        for (int t = wu * 8; t < wu * 8 + 8; t++) {
            int hi = hp[(long)b * TT + t];
            float2 e = *(const float2*)&E[(long)hi * DD + 2 * lane];
            acc.x += e.x * sc;
            acc.y += e.y * sc;
        }
    }
    // Item-side extra: E[items[b]]
    if (side == 1 && wu == 0) {
        int ii = items[b];
        float2 e = *(const float2*)&E[(long)ii * DD + 2 * lane];
        acc.x += e.x;
        acc.y += e.y;
    }

    sAcc[warp][lane] = acc;
    __syncthreads();

    if (warp == 0) {
        float2 u = sAcc[0][lane];
        float2 v = sAcc[4][lane];
        #pragma unroll
        for (int w = 1; w < 4; w++) {
            u.x += sAcc[w][lane].x;     u.y += sAcc[w][lane].y;
            v.x += sAcc[4 + w][lane].x; v.y += sAcc[4 + w][lane].y;
        }
        float d = u.x * v.x + u.y * v.y;
        #pragma unroll
        for (int off = 16; off; off >>= 1)
            d += __shfl_xor_sync(0xffffffffu, d, off);
        if (lane == 0) out[b] = 1.f / (1.f + __expf(-d));
    }
}

// ---------------------------------------------------------------------------
// launch. Inputs (metadata order):
//  0 items, 1 user_h, 2 user_r, 3 user_t, 4 user_nh, 5 user_nr, 6 user_nt,
//  7 item_h, 8 item_r, 9 item_t, 10 item_nh, 11 item_nr, 12 item_nt,
//  13 entity_emb, 14 relation_emb, 15 W_GAT, 16 a_GAT
// ---------------------------------------------------------------------------
extern "C" void kernel_launch(void* const* d_in, const int* in_sizes, int n_in,
                              void* d_out, int out_size) {
    const int*   items   = (const int*)d_in[0];
    const int*   user_h  = (const int*)d_in[1];
    const int*   user_t  = (const int*)d_in[3];
    const int*   user_nh = (const int*)d_in[4];
    const int*   user_nr = (const int*)d_in[5];
    const int*   user_nt = (const int*)d_in[6];
    const int*   item_h  = (const int*)d_in[7];
    const int*   item_t  = (const int*)d_in[9];
    const int*   item_nh = (const int*)d_in[10];
    const int*   item_nr = (const int*)d_in[11];
    const int*   item_nt = (const int*)d_in[12];
    const float* E       = (const float*)d_in[13];
    const float* R       = (const float*)d_in[14];
    const float* W       = (const float*)d_in[15];
    const float* a       = (const float*)d_in[16];
    float* out = (float*)d_out;

    const int B = in_sizes[0];
    int L = in_sizes[1] / (B * TT);
    if (L < 1) L = 1;
    int NE = in_sizes[13] / DD;
    if (NE > TDOT_MAX) NE = TDOT_MAX;

    ckgat_prep<<<1, 64>>>(W, a, R);
    ckgat_tdot<<<(NE + 7) / 8, 256>>>(E, NE);
    ckgat_fused<<<B, 256>>>(items, user_h, user_t, user_nh, user_nr, user_nt,
                            item_h, item_t, item_nh, item_nr, item_nt,
                            E, W, out, B, L);
}